// round 7
// baseline (speedup 1.0000x reference)
#include <cuda_runtime.h>
#include <math.h>

#define NB   296
#define NT   256
#define RP   68                 // padded row stride
#define HSP  (512*RP)           // padded [h][s] matrix
#define LSZ  (65*RP)            // padded [a][b] logits
#define ULL  unsigned long long

// ------------------------- scratch (device globals) -------------------------
__device__ float g_K[3][HSP];          // K per head slot (RED targets)
__device__ float g_Q[3][HSP];
__device__ float g_V[3][HSP];
__device__ float g_L[3][LSZ];          // logits (RED target)
__device__ float g_y[HSP];             // next-layer input (RED target, relu at read)
__device__ float g_C[65*1536];         // concat buffer
__device__ float g_zp[8][1024];        // fc1 partials
__device__ float g_t[512];
__device__ ULL   g_bar[24];            // monotonic barrier counters

// ------------------------- helpers ------------------------------------------
#define FMA2(acc, a, b) asm("fma.rn.f32x2 %0, %1, %2, %0;" : "+l"(acc) : "l"(a), "l"(b))
#define PACK2(d, x)     asm("mov.b64 %0, {%1, %1};" : "=l"(d) : "f"(x))
#define UNPK2(lo, hi, v) asm("mov.b64 {%0, %1}, %2;" : "=f"(lo), "=f"(hi) : "l"(v))

__device__ __forceinline__ void redf(float* p, float v) {
    asm volatile("red.global.add.f32 [%0], %1;" :: "l"(p), "f"(v) : "memory");
}

__device__ __forceinline__ void gbar(int k) {
    __threadfence();
    __syncthreads();
    if (threadIdx.x == 0) {
        ULL* p = &g_bar[k];
        ULL old, cur;
        asm volatile("atom.release.gpu.add.u64 %0, [%1], 1;"
                     : "=l"(old) : "l"(p) : "memory");
        ULL target = old - (old % (ULL)NB) + (ULL)NB;
        do {
            asm volatile("ld.acquire.gpu.u64 %0, [%1];"
                         : "=l"(cur) : "l"(p) : "memory");
        } while (cur < target);
    }
    __syncthreads();
}

__device__ __forceinline__ void pf_range(const float* p, int nfloat) {
    int lines = nfloat >> 5;
    for (int i = blockIdx.x * NT + threadIdx.x; i < lines; i += NB * NT)
        asm volatile("prefetch.global.L2 [%0];" :: "l"(p + (i << 5)));
}

__device__ __forceinline__ void zero4(float* p, int nfloat) {
    for (int i = blockIdx.x * NT + threadIdx.x; i < (nfloat >> 2); i += NB * NT)
        ((float4*)p)[i] = make_float4(0.f, 0.f, 0.f, 0.f);
}

// shared pool (floats): GEMM A0[1056] A1[1056] B0[1088] B1[1088] = 4288
// LOGITS Ks[2176] Qs[2176] = 4352 ; ATT Ls[4420] Vs[2176] = 6596
#define SMEM_F 6608

// =============================================================================
// GEMM item: RED{out[m,s] += sum_k A[m,k]*B[k,s]}.  m-tile 64, k-chunk 16.
// MODE: 0 = B from relu(g_y), 1 = linear (A col-access, B from g_C), 2 = emb*x
// lane -> m {lane, lane+32}; warp w(0..7) -> s {8w..8w+7}; w0 also s=64.
// =============================================================================
template<int MODE>
__device__ __forceinline__ void gemm_prefetch(const float* __restrict__ A,
        int mbase, int kb, const float* __restrict__ emb,
        const float* __restrict__ inp, float a4[4], float b5[5]) {
    const int tid = threadIdx.x;
    if (MODE == 1) {
        int k = tid >> 6, m = tid & 63;
#pragma unroll
        for (int r = 0; r < 4; r++)
            a4[r] = A[(kb + k + 4 * r) * 512 + mbase + m];
        int s = tid >> 4, c = tid & 15;
#pragma unroll
        for (int r = 0; r < 4; r++)
            b5[r] = __ldcg(&g_C[(s + 16 * r) * 1536 + kb + c]);
        b5[4] = (tid < 16) ? __ldcg(&g_C[64 * 1536 + kb + tid]) : 0.f;
    } else {
        int m = tid >> 4, k = tid & 15;
#pragma unroll
        for (int r = 0; r < 4; r++)
            a4[r] = A[(mbase + m + 16 * r) * 512 + kb + k];
        if (MODE == 0) {
#pragma unroll
            for (int r = 0; r < 4; r++) {
                int j = tid + 256 * r;
                b5[r] = fmaxf(__ldcg(&g_y[(kb + j / 65) * RP + j % 65]), 0.f);
            }
            b5[4] = (tid < 16) ? fmaxf(__ldcg(&g_y[(kb + 15) * RP + 49 + tid]), 0.f) : 0.f;
        } else {
#pragma unroll
            for (int r = 0; r < 4; r++) {
                int j = tid + 256 * r;
                int s = j % 65;
                float x = (s < 64) ? __ldg(&inp[s]) : 1.0f;
                b5[r] = emb[(kb + j / 65) * 65 + s] * x;
            }
            if (tid < 16) {
                int s = 49 + tid;
                float x = (s < 64) ? __ldg(&inp[s]) : 1.0f;
                b5[4] = emb[(kb + 15) * 65 + s] * x;
            } else b5[4] = 0.f;
        }
    }
}

template<int MODE>
__device__ __forceinline__ void gemm_store(float* At, float* Bs,
        const float a4[4], const float b5[5]) {
    const int tid = threadIdx.x;
    if (MODE == 1) {
        int k = tid >> 6, m = tid & 63;
#pragma unroll
        for (int r = 0; r < 4; r++) At[(k + 4 * r) * 66 + m] = a4[r];
        int s = tid >> 4, c = tid & 15;
#pragma unroll
        for (int r = 0; r < 4; r++) Bs[c * RP + s + 16 * r] = b5[r];
        if (tid < 16) Bs[tid * RP + 64] = b5[4];
    } else {
        int m = tid >> 4, k = tid & 15;
#pragma unroll
        for (int r = 0; r < 4; r++) At[k * 66 + m + 16 * r] = a4[r];
#pragma unroll
        for (int r = 0; r < 4; r++) {
            int j = tid + 256 * r;
            Bs[(j / 65) * RP + j % 65] = b5[r];
        }
        if (tid < 16) Bs[15 * RP + 49 + tid] = b5[4];
    }
}

template<int NCH, int MODE>
__device__ __forceinline__ void gemm_item(float* sm, const float* __restrict__ A,
        int mbase, int kb0, const float* __restrict__ emb,
        const float* __restrict__ inp, float* __restrict__ outp) {
    const int tid = threadIdx.x, lane = tid & 31, w = tid >> 5;
    float* Ab0 = sm;          float* Ab1 = sm + 1056;
    float* Bb0 = sm + 2112;   float* Bb1 = sm + 3200;

    float a4[4], b5[5];
    gemm_prefetch<MODE>(A, mbase, kb0, emb, inp, a4, b5);
    __syncthreads();                       // guard smem vs previous item
    gemm_store<MODE>(Ab0, Bb0, a4, b5);
    __syncthreads();

    ULL acc[2][4];
#pragma unroll
    for (int i = 0; i < 2; i++)
#pragma unroll
        for (int j = 0; j < 4; j++) acc[i][j] = 0;
    float t0 = 0.f, t1 = 0.f;

#pragma unroll
    for (int c = 0; c < NCH; c++) {
        if (c + 1 < NCH)
            gemm_prefetch<MODE>(A, mbase, kb0 + (c + 1) * 16, emb, inp, a4, b5);
        float* At = (c & 1) ? Ab1 : Ab0;
        float* Bs = (c & 1) ? Bb1 : Bb0;
        const float* Bw = Bs + (w << 3);
#pragma unroll
        for (int k = 0; k < 16; k++) {
            float x0 = At[k * 66 + lane];
            float x1 = At[k * 66 + 32 + lane];
            ULL pa0, pa1;
            PACK2(pa0, x0); PACK2(pa1, x1);
            ulonglong2 ba = *(const ulonglong2*)(Bw + k * RP);
            ulonglong2 bb = *(const ulonglong2*)(Bw + k * RP + 4);
            FMA2(acc[0][0], pa0, ba.x); FMA2(acc[0][1], pa0, ba.y);
            FMA2(acc[0][2], pa0, bb.x); FMA2(acc[0][3], pa0, bb.y);
            FMA2(acc[1][0], pa1, ba.x); FMA2(acc[1][1], pa1, ba.y);
            FMA2(acc[1][2], pa1, bb.x); FMA2(acc[1][3], pa1, bb.y);
            if (w == 0) {
                float b64 = Bs[k * RP + 64];
                t0 = fmaf(x0, b64, t0);
                t1 = fmaf(x1, b64, t1);
            }
        }
        if (c + 1 < NCH) {
            gemm_store<MODE>((c & 1) ? Ab0 : Ab1, (c & 1) ? Bb0 : Bb1, a4, b5);
            __syncthreads();
        }
    }
    // accumulate into output via no-return float atomics (live columns only)
    float* o0 = outp + (mbase + lane) * RP + 8 * w;
    float* o1 = outp + (mbase + lane + 32) * RP + 8 * w;
    float lo, hi;
#pragma unroll
    for (int j = 0; j < 4; j++) {
        UNPK2(lo, hi, acc[0][j]); redf(o0 + 2 * j, lo); redf(o0 + 2 * j + 1, hi);
        UNPK2(lo, hi, acc[1][j]); redf(o1 + 2 * j, lo); redf(o1 + 2 * j + 1, hi);
    }
    if (w == 0) {
        redf(outp + (mbase + lane) * RP + 64, t0);
        redf(outp + (mbase + lane + 32) * RP + 64, t1);
    }
}

// ------------------------- kqv phase (+ zero g_L for this layer) ------------
template<int LAYER>
__device__ void phase_kqv(float* sm, const float* __restrict__ wK,
                          const float* __restrict__ wQ, const float* __restrict__ wV,
                          const float* __restrict__ emb, const float* __restrict__ inp) {
    constexpr int nmats = (LAYER == 1) ? 9 : 3;
    constexpr int nkz   = (LAYER == 1) ? 4 : 8;
    constexpr int kspan = 512 / nkz;
    constexpr int per   = nmats * 8;
    constexpr int items = per * nkz;
    for (int it = blockIdx.x; it < items; it += NB) {
        int kz = it / per, rem = it - kz * per;
        int mat = rem >> 3, mtile = rem & 7;
        int type = (LAYER == 1) ? (mat % 3) : mat;
        int head = (LAYER == 1) ? (mat / 3) : 2;
        int slot = (LAYER == 1) ? head : 0;
        const float* A = ((type == 0) ? wK : (type == 1) ? wQ : wV) + head * 262144;
        float* outp = (type == 0) ? g_K[slot] : (type == 1) ? g_Q[slot] : g_V[slot];
        gemm_item<kspan / 16, (LAYER == 1) ? 2 : 0>(sm, A, mtile * 64, kz * kspan,
                                                    emb, inp, outp);
    }
    if (LAYER == 1) zero4(&g_L[0][0], 3 * LSZ);
    else            zero4(&g_L[0][0], LSZ);
}

// ------------------------- logits phase (RED into g_L, h-chunk 32) ----------
template<int LAYER>
__device__ void phase_logits(float* sm) {
    float* Ks = sm;            // [32][68]
    float* Qs = sm + 2176;
    const int tid = threadIdx.x, lane = tid & 31, w = tid >> 5;
    constexpr int slots = (LAYER == 1) ? 3 : 1;
    constexpr int items = slots * 16;
    for (int it = blockIdx.x; it < items; it += NB) {
        int slot = it >> 4, hc = it & 15, h0 = hc * 32;
        __syncthreads();
#pragma unroll 2
        for (int i = tid; i < 544; i += NT) {
            ((float4*)Ks)[i] = __ldcg((const float4*)&g_K[slot][h0 * RP] + i);
            ((float4*)Qs)[i] = __ldcg((const float4*)&g_Q[slot][h0 * RP] + i);
        }
        __syncthreads();
        ULL r0[4] = {0,0,0,0}, r1[4] = {0,0,0,0}, r2[4] = {0,0,0,0};
        float u0 = 0.f, u1 = 0.f, u2 = 0.f;
        for (int h = 0; h < 32; h++) {
            float k0 = Ks[h * RP + lane];
            float k1 = Ks[h * RP + 32 + lane];
            float k2 = Ks[h * RP + 64];
            ULL p0, p1, p2;
            PACK2(p0, k0); PACK2(p1, k1); PACK2(p2, k2);
            ulonglong2 qa = *(const ulonglong2*)(Qs + h * RP + 8 * w);
            ulonglong2 qb = *(const ulonglong2*)(Qs + h * RP + 8 * w + 4);
            FMA2(r0[0], p0, qa.x); FMA2(r0[1], p0, qa.y);
            FMA2(r0[2], p0, qb.x); FMA2(r0[3], p0, qb.y);
            FMA2(r1[0], p1, qa.x); FMA2(r1[1], p1, qa.y);
            FMA2(r1[2], p1, qb.x); FMA2(r1[3], p1, qb.y);
            FMA2(r2[0], p2, qa.x); FMA2(r2[1], p2, qa.y);
            FMA2(r2[2], p2, qb.x); FMA2(r2[3], p2, qb.y);
            if (w == 0) {
                float q64 = Qs[h * RP + 64];
                u0 = fmaf(k0, q64, u0); u1 = fmaf(k1, q64, u1); u2 = fmaf(k2, q64, u2);
            }
        }
        float* L = &g_L[slot][0];
        float lo, hi;
#pragma unroll
        for (int j = 0; j < 4; j++) {
            UNPK2(lo, hi, r0[j]);
            redf(L + lane * RP + 8 * w + 2 * j, lo);
            redf(L + lane * RP + 8 * w + 2 * j + 1, hi);
            UNPK2(lo, hi, r1[j]);
            redf(L + (lane + 32) * RP + 8 * w + 2 * j, lo);
            redf(L + (lane + 32) * RP + 8 * w + 2 * j + 1, hi);
            if (lane == 0) {
                UNPK2(lo, hi, r2[j]);
                redf(L + 64 * RP + 8 * w + 2 * j, lo);
                redf(L + 64 * RP + 8 * w + 2 * j + 1, hi);
            }
        }
        if (w == 0) {
            redf(L + lane * RP + 64, u0);
            redf(L + (lane + 32) * RP + 64, u1);
            if (lane == 0) redf(L + 64 * RP + 64, u2);
        }
    }
}

// ------------------------- att phase (softmax fused; + zero g_y) ------------
template<int LAYER>
__device__ void phase_att(float* sm) {
    float* Ls = sm;            // [65][68]
    float* Vs = sm + 4420;     // [32][68]
    const int tid = threadIdx.x, lane = tid & 31, w = tid >> 5;
    constexpr int slots = (LAYER == 1) ? 3 : 1;
    constexpr int items = slots * 16;
    for (int it = blockIdx.x; it < items; it += NB) {
        int slot = it >> 4, hc = it & 15, h0 = hc * 32;
        int col0 = (LAYER == 1) ? slot * 512 : 1024;
        __syncthreads();
#pragma unroll 2
        for (int i = tid; i < 1105; i += NT)
            ((float4*)Ls)[i] = __ldcg((const float4*)&g_L[slot][0] + i);
#pragma unroll 2
        for (int i = tid; i < 544; i += NT)
            ((float4*)Vs)[i] = __ldcg((const float4*)&g_V[slot][h0 * RP] + i);
        __syncthreads();
        if (tid < 32) { Vs[tid * RP + 65] = 0.f; Vs[tid * RP + 66] = 0.f; Vs[tid * RP + 67] = 0.f; }
        __syncthreads();
        for (int a = w; a < 65; a += 8) {
            float e0 = Ls[a * RP + lane];
            float e1 = Ls[a * RP + 32 + lane];
            float e2 = (lane == 0) ? Ls[a * RP + 64] : -3.0e38f;
            float mx = fmaxf(e0, fmaxf(e1, e2));
#pragma unroll
            for (int off = 16; off > 0; off >>= 1)
                mx = fmaxf(mx, __shfl_xor_sync(0xffffffffu, mx, off));
            float x0 = expf(e0 - mx);
            float x1 = expf(e1 - mx);
            float x2 = (lane == 0) ? expf(e2 - mx) : 0.f;
            float ssum = x0 + x1 + x2;
#pragma unroll
            for (int off = 16; off > 0; off >>= 1)
                ssum += __shfl_xor_sync(0xffffffffu, ssum, off);
            float inv = 1.0f / ssum;
            Ls[a * RP + lane] = x0 * inv;
            Ls[a * RP + 32 + lane] = x1 * inv;
            if (lane == 0) Ls[a * RP + 64] = x2 * inv;
        }
        __syncthreads();
        ULL acc[8] = {0,0,0,0,0,0,0,0};
        ULL acc64 = 0;
        const float* Vrow = Vs + lane * RP;
        for (int p = 0; p < 34; p++) {
            ULL vv = *(const ULL*)(Vrow + 2 * p);
#pragma unroll
            for (int j = 0; j < 8; j++) {
                ULL lp = *(const ULL*)(Ls + (8 * w + j) * RP + 2 * p);
                FMA2(acc[j], lp, vv);
            }
            if (w == 0) {
                ULL l64 = *(const ULL*)(Ls + 64 * RP + 2 * p);
                FMA2(acc64, l64, vv);
            }
        }
#pragma unroll
        for (int j = 0; j < 8; j++) {
            float lo, hi; UNPK2(lo, hi, acc[j]);
            g_C[(8 * w + j) * 1536 + col0 + h0 + lane] = lo + hi;
        }
        if (w == 0) {
            float lo, hi; UNPK2(lo, hi, acc64);
            g_C[64 * 1536 + col0 + h0 + lane] = lo + hi;
        }
    }
    if (LAYER < 3) zero4(g_y, HSP);   // next linear phase REDs into g_y
}

// ------------------------- linear phase (RED into g_y; + zero K/Q/V,L) ------
template<int LAYER>
__device__ void phase_linear(float* sm, const float* __restrict__ W) {
    for (int it = blockIdx.x; it < 192; it += NB) {
        int cc = it >> 3, mtile = it & 7;
        gemm_item<4, 1>(sm, W, mtile * 64, cc * 64, 0, 0, g_y);
    }
    // prepare next layer's RED targets (last read 2 phases ago)
    zero4(&g_K[0][0], HSP);
    zero4(&g_Q[0][0], HSP);
    zero4(&g_V[0][0], HSP);
}

// ------------------------- final chain --------------------------------------
__device__ void phase_fc1(float* sm, const float* __restrict__ W3) {   // [1536][1024]
    float* Crs = sm;
    float* Rs  = sm + 192;
    const int tid = threadIdx.x;
    for (int it = blockIdx.x; it < 64; it += NB) {
        int jt = it & 7, cc = it >> 3;
        int c0 = cc * 192, j0 = jt * 128;
        __syncthreads();
        for (int i = tid; i < 192; i += NT)
            Crs[i] = __ldcg(&g_C[64 * 1536 + c0 + i]);
        __syncthreads();
        int j = j0 + (tid & 127);
        int q = tid >> 7;
        float acc = 0.f;
#pragma unroll 4
        for (int c = q * 96; c < q * 96 + 96; c++)
            acc = fmaf(Crs[c], W3[(c0 + c) * 1024 + j], acc);
        Rs[tid] = acc;
        __syncthreads();
        if (tid < 128) g_zp[cc][j0 + tid] = Rs[tid] + Rs[tid + 128];
    }
}

__device__ void phase_ft(float* sm, const float* __restrict__ W4) {   // [1024][512]
    float* zs = sm;
    float* Rs = sm + 1024;
    const int tid = threadIdx.x, lane = tid & 31, w = tid >> 5;
    for (int it = blockIdx.x; it < 4; it += NB) {
        int h0 = it * 128;
        __syncthreads();
        for (int i = tid; i < 1024; i += NT) {
            float v = 0.f;
#pragma unroll
            for (int c = 0; c < 8; c++) v += __ldcg(&g_zp[c][i]);
            zs[i] = fmaxf(v, 0.f);
        }
        __syncthreads();
        int hh = h0 + lane * 4;
        float4 a = make_float4(0.f, 0.f, 0.f, 0.f);
#pragma unroll 4
        for (int k = w * 128; k < w * 128 + 128; k++) {
            float zv = zs[k];
            float4 wr = *(const float4*)(&W4[k * 512 + hh]);
            a.x = fmaf(zv, wr.x, a.x); a.y = fmaf(zv, wr.y, a.y);
            a.z = fmaf(zv, wr.z, a.z); a.w = fmaf(zv, wr.w, a.w);
        }
        Rs[w * 128 + lane * 4 + 0] = a.x;
        Rs[w * 128 + lane * 4 + 1] = a.y;
        Rs[w * 128 + lane * 4 + 2] = a.z;
        Rs[w * 128 + lane * 4 + 3] = a.w;
        __syncthreads();
        if (tid < 128) {
            float s = 0.f;
#pragma unroll
            for (int ww = 0; ww < 8; ww++) s += Rs[ww * 128 + tid];
            g_t[h0 + tid] = tanhf(s);
        }
    }
}

__device__ void phase_fout(float* sm, const float* __restrict__ W5,
                           float* __restrict__ out) {   // [512][64]
    float* ts = sm;
    float* Rs = sm + 512;
    const int tid = threadIdx.x, lane = tid & 31, w = tid >> 5;
    for (int i = tid; i < 512; i += NT) ts[i] = __ldcg(&g_t[i]);
    __syncthreads();
    float acc0 = 0.f, acc1 = 0.f;
    for (int k = w * 64; k < w * 64 + 64; k++) {
        float tv = ts[k];
        acc0 = fmaf(tv, W5[k * 64 + lane], acc0);
        acc1 = fmaf(tv, W5[k * 64 + 32 + lane], acc1);
    }
    Rs[w * 64 + lane] = acc0;
    Rs[w * 64 + 32 + lane] = acc1;
    __syncthreads();
    if (tid < 64) {
        float s = 0.f;
#pragma unroll
        for (int ww = 0; ww < 8; ww++) s += Rs[ww * 64 + tid];
        out[tid] = s;
    }
}

// =============================================================================
__global__ __launch_bounds__(NT, 2)
void persist_kernel(const float* __restrict__ inp, const float* __restrict__ emb,
                    const float* __restrict__ wk, const float* __restrict__ wq,
                    const float* __restrict__ wv,
                    const float* __restrict__ l1, const float* __restrict__ l2,
                    const float* __restrict__ l3, const float* __restrict__ l4,
                    const float* __restrict__ l5, float* __restrict__ out) {
    __shared__ __align__(16) float sm[SMEM_F];
    const int HH = 512 * 512 * 3;

    // init: L2 prefetch of live weight ranges + zero layer-1 RED targets
    pf_range(wk, 786432); pf_range(wk + 1310720, 262144); pf_range(wk + 2097152, 262144);
    pf_range(wq, 786432); pf_range(wq + 1310720, 262144); pf_range(wq + 2097152, 262144);
    pf_range(wv, 786432); pf_range(wv + 1310720, 262144); pf_range(wv + 2097152, 262144);
    pf_range(l1, 786432); pf_range(l2, 786432);
    pf_range(l3, 1572864); pf_range(l4, 524288); pf_range(l5, 32768);
    pf_range(emb, 33280);
    zero4(&g_K[0][0], 3 * HSP);
    zero4(&g_Q[0][0], 3 * HSP);
    zero4(&g_V[0][0], 3 * HSP);
    gbar(0);

    // ---- layer 1 ----
    phase_kqv<1>(sm, wk, wq, wv, emb, inp);                     gbar(1);
    phase_logits<1>(sm);                                        gbar(2);
    phase_att<1>(sm);                                           gbar(3);
    phase_linear<1>(sm, l1);                                    gbar(4);
    // ---- layer 2 ----
    phase_kqv<2>(sm, wk + HH, wq + HH, wv + HH, emb, inp);      gbar(5);
    phase_logits<2>(sm);                                        gbar(6);
    phase_att<2>(sm);                                           gbar(7);
    phase_linear<2>(sm, l2);                                    gbar(8);
    // ---- layer 3 ----
    phase_kqv<3>(sm, wk + 2 * HH, wq + 2 * HH, wv + 2 * HH, emb, inp); gbar(9);
    phase_logits<3>(sm);                                        gbar(10);
    phase_att<3>(sm);                                           gbar(11);
    // ---- final chain ----
    phase_fc1(sm, l3);                                          gbar(12);
    phase_ft(sm, l4);                                           gbar(13);
    if (blockIdx.x == 0) phase_fout(sm, l5, out);
}

// ------------------------- launcher ----------------------------------------
extern "C" void kernel_launch(void* const* d_in, const int* in_sizes, int n_in,
                              void* d_out, int out_size) {
    const float *inp = 0, *emb = 0, *l3 = 0, *l4 = 0, *l5 = 0;
    const float *tri[3] = {0, 0, 0};  int ntri = 0;
    const float *pr[2]  = {0, 0};     int npr  = 0;
    for (int i = 0; i < n_in; i++) {
        const float* p = (const float*)d_in[i];
        switch (in_sizes[i]) {
            case 64:      inp = p; break;
            case 33280:   emb = p; break;
            case 2359296: if (ntri < 3) tri[ntri++] = p; break;
            case 786432:  if (npr  < 2) pr[npr++]   = p; break;
            case 1572864: l3 = p; break;
            case 524288:  l4 = p; break;
            case 32768:   l5 = p; break;
            default: break;
        }
    }
    const float *wq, *wk, *wv;
    if (n_in > 0 && in_sizes[0] == 33280) { wk = tri[0]; wq = tri[1]; wv = tri[2]; }
    else                                  { wq = tri[0]; wk = tri[1]; wv = tri[2]; }
    const float *l1 = pr[0], *l2 = pr[1];
    float* out = (float*)d_out;

    persist_kernel<<<NB, NT>>>(inp, emb, wk, wq, wv, l1, l2, l3, l4, l5, out);
}

// round 9
// speedup vs baseline: 1.2361x; 1.2361x over previous
#include <cuda_runtime.h>
#include <stdint.h>
#include <math.h>

#define NB   296
#define NT   256
#define RP   68                 // global padded row stride
#define HSP  (512*RP)
#define LSZ  (65*RP)
#define ULL  unsigned long long

// ------------------------- scratch (device globals) -------------------------
__device__ float g_y[HSP];             // current y [512][68]
__device__ float g_P[8][9][HSP];       // kqv partials [kz][mat]; reduced into [0][mat]
__device__ float g_Lp[8][3][LSZ];      // logits partials [hcc][slot]; reduced into [0][slot]
__device__ float g_C[65*1536];         // concat buffer
__device__ float g_lp[24][HSP];        // linear partials [cc]
__device__ float g_zp[8][1024];
__device__ float g_t[512];
__device__ ULL   g_bar[24];

// ------------------------- helpers ------------------------------------------
#define FMA2(acc, a, b) asm("fma.rn.f32x2 %0, %1, %2, %0;" : "+l"(acc) : "l"(a), "l"(b))
#define PACK2(d, x)     asm("mov.b64 %0, {%1, %1};" : "=l"(d) : "f"(x))
#define UNPK2(lo, hi, v) asm("mov.b64 {%0, %1}, %2;" : "=f"(lo), "=f"(hi) : "l"(v))

#define MMA_TF32(d, a0, a1, a2, a3, b0, b1) \
    asm("mma.sync.aligned.m16n8k8.row.col.f32.tf32.tf32.f32 " \
        "{%0,%1,%2,%3}, {%4,%5,%6,%7}, {%8,%9}, {%0,%1,%2,%3};" \
        : "+f"(d[0]), "+f"(d[1]), "+f"(d[2]), "+f"(d[3]) \
        : "r"(a0), "r"(a1), "r"(a2), "r"(a3), "r"(b0), "r"(b1))

__device__ __forceinline__ float tf32r(float f) {
    uint32_t u;
    asm("cvt.rna.tf32.f32 %0, %1;" : "=r"(u) : "f"(f));
    return __uint_as_float(u);
}

__device__ __forceinline__ void gbar(int k) {
    __threadfence();
    __syncthreads();
    if (threadIdx.x == 0) {
        ULL* p = &g_bar[k];
        ULL old, cur;
        asm volatile("atom.release.gpu.add.u64 %0, [%1], 1;"
                     : "=l"(old) : "l"(p) : "memory");
        ULL target = old - (old % (ULL)NB) + (ULL)NB;
        do {
            asm volatile("ld.acquire.gpu.u64 %0, [%1];"
                         : "=l"(cur) : "l"(p) : "memory");
        } while (cur < target);
    }
    __syncthreads();
}

__device__ __forceinline__ void pf_range(const float* p, int nfloat) {
    int lines = nfloat >> 5;
    for (int i = blockIdx.x * NT + threadIdx.x; i < lines; i += NB * NT)
        asm volatile("prefetch.global.L2 [%0];" :: "l"(p + (i << 5)));
}

// shared pool (floats):
// GEMM: A0[1152] A1[1152] B0[1152] B1[1152] Tr[4352] = 8960
// LOGITS Ks[4352] Qs[4352] Sm[4420] = 13124 ; ATT Ls[4420] Vs[2176] = 6596
#define SMEM_F 13124

// =============================================================================
// GEMM item via tf32 mma.sync m16n8k8: out[m,s] = sum_k A[m,k]*B[k,s]
// m-tile 64, k-chunk 16 (2 k-frags). Warp w -> n-slice s in [8w, 8w+8).
// Column 64 lives in a zero-padded 9th slice (B cols 64-71); its 8
// (mfrag x kfrag) MMAs are distributed one per warp and combined in Tr.
// A smem [16][72] (k-major), B smem [16][72]; stride 72 => conflict-free frags.
// =============================================================================
template<int MODE>
__device__ __forceinline__ void gemm_prefetch(const float* __restrict__ A,
        int mbase, int kb, const float* __restrict__ emb,
        const float* __restrict__ inp, float a4[4], float b5[5]) {
    const int tid = threadIdx.x;
    if (MODE == 1) {
        int k = tid >> 6, m = tid & 63;
#pragma unroll
        for (int r = 0; r < 4; r++)
            a4[r] = A[(kb + k + 4 * r) * 512 + mbase + m];
        int s = tid >> 4, c = tid & 15;
#pragma unroll
        for (int r = 0; r < 4; r++)
            b5[r] = __ldcg(&g_C[(s + 16 * r) * 1536 + kb + c]);
        b5[4] = (tid < 16) ? __ldcg(&g_C[64 * 1536 + kb + tid]) : 0.f;
    } else {
        int m = tid >> 4, k = tid & 15;
#pragma unroll
        for (int r = 0; r < 4; r++)
            a4[r] = A[(mbase + m + 16 * r) * 512 + kb + k];
        if (MODE == 0) {
#pragma unroll
            for (int r = 0; r < 4; r++) {
                int j = tid + 256 * r;
                b5[r] = __ldcg(&g_y[(kb + j / 65) * RP + j % 65]);
            }
            b5[4] = (tid < 16) ? __ldcg(&g_y[(kb + 15) * RP + 49 + tid]) : 0.f;
        } else {
#pragma unroll
            for (int r = 0; r < 4; r++) {
                int j = tid + 256 * r;
                int s = j % 65;
                float x = (s < 64) ? __ldg(&inp[s]) : 1.0f;
                b5[r] = emb[(kb + j / 65) * 65 + s] * x;
            }
            if (tid < 16) {
                int s = 49 + tid;
                float x = (s < 64) ? __ldg(&inp[s]) : 1.0f;
                b5[4] = emb[(kb + 15) * 65 + s] * x;
            } else b5[4] = 0.f;
        }
    }
}

template<int MODE>
__device__ __forceinline__ void gemm_store(float* At, float* Bs,
        const float a4[4], const float b5[5]) {
    const int tid = threadIdx.x;
    if (MODE == 1) {
        int k = tid >> 6, m = tid & 63;
#pragma unroll
        for (int r = 0; r < 4; r++) At[(k + 4 * r) * 72 + m] = tf32r(a4[r]);
        int s = tid >> 4, c = tid & 15;
#pragma unroll
        for (int r = 0; r < 4; r++) Bs[c * 72 + s + 16 * r] = tf32r(b5[r]);
        if (tid < 16) Bs[tid * 72 + 64] = tf32r(b5[4]);
    } else {
        int m = tid >> 4, k = tid & 15;
#pragma unroll
        for (int r = 0; r < 4; r++) At[k * 72 + m + 16 * r] = tf32r(a4[r]);
#pragma unroll
        for (int r = 0; r < 4; r++) {
            int j = tid + 256 * r;
            Bs[(j / 65) * 72 + j % 65] = tf32r(b5[r]);
        }
        if (tid < 16) Bs[15 * 72 + 49 + tid] = tf32r(b5[4]);
    }
    // zero pad columns 65..71 (16 rows x 7 cols)
    if (tid < 112) Bs[(tid / 7) * 72 + 65 + tid % 7] = 0.f;
}

template<int NCH, int MODE>
__device__ __forceinline__ void gemm_item(float* sm, const float* __restrict__ A,
        int mbase, int kb0, const float* __restrict__ emb,
        const float* __restrict__ inp, float* __restrict__ outp) {
    const int tid = threadIdx.x, lane = tid & 31, w = tid >> 5;
    const int gid = lane >> 2, tig = lane & 3;
    float* Ab0 = sm;          float* Ab1 = sm + 1152;
    float* Bb0 = sm + 2304;   float* Bb1 = sm + 3456;
    float* Tr  = sm + 4608;   // [64][68]

    float a4[4], b5[5];
    gemm_prefetch<MODE>(A, mbase, kb0, emb, inp, a4, b5);
    __syncthreads();                    // guard smem vs previous item
    gemm_store<MODE>(Ab0, Bb0, a4, b5);
    __syncthreads();

    float d[4][4];
#pragma unroll
    for (int i = 0; i < 4; i++)
#pragma unroll
        for (int j = 0; j < 4; j++) d[i][j] = 0.f;
    float d8[4] = {0.f, 0.f, 0.f, 0.f};
    const int mfw = w & 3, kfw = w >> 2;   // slice-8 assignment

#pragma unroll
    for (int c = 0; c < NCH; c++) {
        if (c + 1 < NCH)
            gemm_prefetch<MODE>(A, mbase, kb0 + (c + 1) * 16, emb, inp, a4, b5);
        const float* At = (c & 1) ? Ab1 : Ab0;
        const float* Bs = (c & 1) ? Bb1 : Bb0;
#pragma unroll
        for (int kf = 0; kf < 2; kf++) {
            int kr = kf * 8;
            uint32_t b0 = __float_as_uint(Bs[(kr + tig) * 72 + 8 * w + gid]);
            uint32_t b1 = __float_as_uint(Bs[(kr + tig + 4) * 72 + 8 * w + gid]);
#pragma unroll
            for (int mf = 0; mf < 4; mf++) {
                int mc = mf * 16 + gid;
                uint32_t a0 = __float_as_uint(At[(kr + tig) * 72 + mc]);
                uint32_t a1 = __float_as_uint(At[(kr + tig) * 72 + mc + 8]);
                uint32_t a2 = __float_as_uint(At[(kr + tig + 4) * 72 + mc]);
                uint32_t a3 = __float_as_uint(At[(kr + tig + 4) * 72 + mc + 8]);
                MMA_TF32(d[mf], a0, a1, a2, a3, b0, b1);
            }
        }
        {   // slice 8 (cols 64-71): this warp's (mfw, kfw) fragment
            int kr = kfw * 8;
            uint32_t b0 = __float_as_uint(Bs[(kr + tig) * 72 + 64 + gid]);
            uint32_t b1 = __float_as_uint(Bs[(kr + tig + 4) * 72 + 64 + gid]);
            int mc = mfw * 16 + gid;
            uint32_t a0 = __float_as_uint(At[(kr + tig) * 72 + mc]);
            uint32_t a1 = __float_as_uint(At[(kr + tig) * 72 + mc + 8]);
            uint32_t a2 = __float_as_uint(At[(kr + tig + 4) * 72 + mc]);
            uint32_t a3 = __float_as_uint(At[(kr + tig + 4) * 72 + mc + 8]);
            MMA_TF32(d8, a0, a1, a2, a3, b0, b1);
        }
        if (c + 1 < NCH) {
            gemm_store<MODE>((c & 1) ? Ab0 : Ab1, (c & 1) ? Bb0 : Bb1, a4, b5);
            __syncthreads();
        }
    }
    // main-slice D -> Tr (cols 0-63)
#pragma unroll
    for (int mf = 0; mf < 4; mf++) {
        int cc = 8 * w + tig * 2;
        *(float2*)&Tr[(mf * 16 + gid) * RP + cc]     = make_float2(d[mf][0], d[mf][1]);
        *(float2*)&Tr[(mf * 16 + gid + 8) * RP + cc] = make_float2(d[mf][2], d[mf][3]);
    }
    // slice-8: kfrag 0 stores, kfrag 1 adds (cols 64-67; cols >=68 are zero)
    if (kfw == 0 && tig < 2) {
        *(float2*)&Tr[(mfw * 16 + gid) * RP + 64 + tig * 2]     = make_float2(d8[0], d8[1]);
        *(float2*)&Tr[(mfw * 16 + gid + 8) * RP + 64 + tig * 2] = make_float2(d8[2], d8[3]);
    }
    __syncthreads();
    if (kfw == 1 && tig < 2) {
        float2* p0 = (float2*)&Tr[(mfw * 16 + gid) * RP + 64 + tig * 2];
        float2 v0 = *p0; v0.x += d8[0]; v0.y += d8[1]; *p0 = v0;
        float2* p1 = (float2*)&Tr[(mfw * 16 + gid + 8) * RP + 64 + tig * 2];
        float2 v1 = *p1; v1.x += d8[2]; v1.y += d8[3]; *p1 = v1;
    }
    __syncthreads();
    for (int i = tid; i < 64 * RP; i += NT)
        outp[mbase * RP + i] = Tr[i];
}

// ------------------------- kqv phase ----------------------------------------
template<int LAYER>
__device__ void phase_kqv(float* sm, const float* __restrict__ wK,
                          const float* __restrict__ wQ, const float* __restrict__ wV,
                          const float* __restrict__ emb, const float* __restrict__ inp) {
    constexpr int nmats = (LAYER == 1) ? 9 : 3;
    constexpr int nkz   = (LAYER == 1) ? 4 : 8;
    constexpr int kspan = 512 / nkz;
    constexpr int per   = nmats * 8;
    constexpr int items = per * nkz;
    for (int it = blockIdx.x; it < items; it += NB) {
        int kz = it / per, rem = it - kz * per;
        int mat = rem >> 3, mtile = rem & 7;
        int type = (LAYER == 1) ? (mat % 3) : mat;
        int head = (LAYER == 1) ? (mat / 3) : 2;
        const float* A = ((type == 0) ? wK : (type == 1) ? wQ : wV) + head * 262144;
        gemm_item<kspan / 16, (LAYER == 1) ? 2 : 0>(sm, A, mtile * 64, kz * kspan,
                                                    emb, inp, &g_P[kz][mat][0]);
    }
}

// ------------------------- reduce kqv partials -------------------------------
template<int LAYER>
__device__ void phase_reduce() {
    constexpr int nmats = (LAYER == 1) ? 9 : 3;
    constexpr int nz    = (LAYER == 1) ? 4 : 8;
    constexpr int Q4    = HSP / 4;
    for (int j = blockIdx.x * NT + threadIdx.x; j < nmats * Q4; j += NB * NT) {
        int mat = j / Q4, i = j - mat * Q4;
        float4 v = __ldcg((const float4*)&g_P[0][mat][4 * i]);
#pragma unroll
        for (int z = 1; z < nz; z++) {
            float4 u = __ldcg((const float4*)&g_P[z][mat][4 * i]);
            v.x += u.x; v.y += u.y; v.z += u.z; v.w += u.w;
        }
        *(float4*)&g_P[0][mat][4 * i] = v;
    }
}

// ------------------------- logits phase (h-chunk 64) ------------------------
template<int LAYER>
__device__ void phase_logits(float* sm) {
    float* Ks = sm;            // [64][68]
    float* Qs = sm + 4352;
    float* Sm = sm + 8704;     // [65][68]
    const int tid = threadIdx.x, lane = tid & 31, w = tid >> 5;
    constexpr int slots = (LAYER == 1) ? 3 : 1;
    constexpr int items = slots * 8;
    for (int it = blockIdx.x; it < items; it += NB) {
        int slot = it >> 3, hcc = it & 7, h0 = hcc * 64;
        int matK = (LAYER == 1) ? slot * 3 : 0;
        int matQ = matK + 1;
        __syncthreads();
#pragma unroll 2
        for (int i = tid; i < 1088; i += NT) {
            *(float4*)&Ks[4 * i] = __ldcg((const float4*)&g_P[0][matK][h0 * RP + 4 * i]);
            *(float4*)&Qs[4 * i] = __ldcg((const float4*)&g_P[0][matQ][h0 * RP + 4 * i]);
        }
        if (tid < 65) { Sm[tid * RP + 65] = 0.f; Sm[tid * RP + 66] = 0.f; Sm[tid * RP + 67] = 0.f; }
        __syncthreads();
        ULL r0[4] = {0,0,0,0}, r1[4] = {0,0,0,0}, r2[4] = {0,0,0,0};
        float u0 = 0.f, u1 = 0.f, u2 = 0.f;
        for (int h = 0; h < 64; h++) {
            float k0 = Ks[h * RP + lane];
            float k1 = Ks[h * RP + 32 + lane];
            float k2 = Ks[h * RP + 64];
            ULL p0, p1, p2;
            PACK2(p0, k0); PACK2(p1, k1); PACK2(p2, k2);
            ulonglong2 qa = *(const ulonglong2*)(Qs + h * RP + 8 * w);
            ulonglong2 qb = *(const ulonglong2*)(Qs + h * RP + 8 * w + 4);
            FMA2(r0[0], p0, qa.x); FMA2(r0[1], p0, qa.y);
            FMA2(r0[2], p0, qb.x); FMA2(r0[3], p0, qb.y);
            FMA2(r1[0], p1, qa.x); FMA2(r1[1], p1, qa.y);
            FMA2(r1[2], p1, qb.x); FMA2(r1[3], p1, qb.y);
            FMA2(r2[0], p2, qa.x); FMA2(r2[1], p2, qa.y);
            FMA2(r2[2], p2, qb.x); FMA2(r2[3], p2, qb.y);
            if (w == 0) {
                float q64 = Qs[h * RP + 64];
                u0 = fmaf(k0, q64, u0); u1 = fmaf(k1, q64, u1); u2 = fmaf(k2, q64, u2);
            }
        }
        *(ulonglong2*)(Sm + lane * RP + 8 * w)     = make_ulonglong2(r0[0], r0[1]);
        *(ulonglong2*)(Sm + lane * RP + 8 * w + 4) = make_ulonglong2(r0[2], r0[3]);
        *(ulonglong2*)(Sm + (lane + 32) * RP + 8 * w)     = make_ulonglong2(r1[0], r1[1]);
        *(ulonglong2*)(Sm + (lane + 32) * RP + 8 * w + 4) = make_ulonglong2(r1[2], r1[3]);
        if (lane == 0) {
            *(ulonglong2*)(Sm + 64 * RP + 8 * w)     = make_ulonglong2(r2[0], r2[1]);
            *(ulonglong2*)(Sm + 64 * RP + 8 * w + 4) = make_ulonglong2(r2[2], r2[3]);
        }
        if (w == 0) {
            Sm[lane * RP + 64] = u0;
            Sm[(lane + 32) * RP + 64] = u1;
            if (lane == 0) Sm[64 * RP + 64] = u2;
        }
        __syncthreads();
        float* Lp = &g_Lp[hcc][slot][0];
        for (int i = tid; i < LSZ; i += NT) Lp[i] = Sm[i];
    }
}

// ------------------------- reduce logits partials ----------------------------
template<int LAYER>
__device__ void phase_lred() {
    constexpr int slots = (LAYER == 1) ? 3 : 1;
    constexpr int Q4 = LSZ / 4;
    for (int j = blockIdx.x * NT + threadIdx.x; j < slots * Q4; j += NB * NT) {
        int slot = j / Q4, i = j - slot * Q4;
        float4 v = __ldcg((const float4*)&g_Lp[0][slot][4 * i]);
#pragma unroll
        for (int c = 1; c < 8; c++) {
            float4 u = __ldcg((const float4*)&g_Lp[c][slot][4 * i]);
            v.x += u.x; v.y += u.y; v.z += u.z; v.w += u.w;
        }
        *(float4*)&g_Lp[0][slot][4 * i] = v;
    }
}

// ------------------------- att phase (softmax fused) ------------------------
template<int LAYER>
__device__ void phase_att(float* sm) {
    float* Ls = sm;            // [65][68]
    float* Vs = sm + 4420;     // [32][68]
    const int tid = threadIdx.x, lane = tid & 31, w = tid >> 5;
    constexpr int slots = (LAYER == 1) ? 3 : 1;
    constexpr int items = slots * 16;
    for (int it = blockIdx.x; it < items; it += NB) {
        int slot = it >> 4, hc = it & 15, h0 = hc * 32;
        int matV = (LAYER == 1) ? slot * 3 + 2 : 2;
        int col0 = (LAYER == 1) ? slot * 512 : 1024;
        __syncthreads();
#pragma unroll 2
        for (int i = tid; i < 1105; i += NT)
            ((float4*)Ls)[i] = __ldcg((const float4*)&g_Lp[0][slot][0] + i);
#pragma unroll 2
        for (int i = tid; i < 544; i += NT)
            ((float4*)Vs)[i] = __ldcg((const float4*)&g_P[0][matV][h0 * RP] + i);
        __syncthreads();
        if (tid < 32) { Vs[tid * RP + 65] = 0.f; Vs[tid * RP + 66] = 0.f; Vs[tid * RP + 67] = 0.f; }
        __syncthreads();
        for (int a = w; a < 65; a += 8) {
            float e0 = Ls[a * RP + lane];
            float e1 = Ls[a * RP + 32 + lane];
            float e2 = (lane == 0) ? Ls[a * RP + 64] : -3.0e38f;
            float mx = fmaxf(e0, fmaxf(e1, e2));
#pragma unroll
            for (int off = 16; off > 0; off >>= 1)
                mx = fmaxf(mx, __shfl_xor_sync(0xffffffffu, mx, off));
            float x0 = expf(e0 - mx);
            float x1 = expf(e1 - mx);
            float x2 = (lane == 0) ? expf(e2 - mx) : 0.f;
            float ssum = x0 + x1 + x2;
#pragma unroll
            for (int off = 16; off > 0; off >>= 1)
                ssum += __shfl_xor_sync(0xffffffffu, ssum, off);
            float inv = 1.0f / ssum;
            Ls[a * RP + lane] = x0 * inv;
            Ls[a * RP + 32 + lane] = x1 * inv;
            if (lane == 0) Ls[a * RP + 64] = x2 * inv;
        }
        __syncthreads();
        ULL acc[8] = {0,0,0,0,0,0,0,0};
        ULL acc64 = 0;
        const float* Vrow = Vs + lane * RP;
        for (int p = 0; p < 34; p++) {
            ULL vv = *(const ULL*)(Vrow + 2 * p);
#pragma unroll
            for (int j = 0; j < 8; j++) {
                ULL lp = *(const ULL*)(Ls + (8 * w + j) * RP + 2 * p);
                FMA2(acc[j], lp, vv);
            }
            if (w == 0) {
                ULL l64 = *(const ULL*)(Ls + 64 * RP + 2 * p);
                FMA2(acc64, l64, vv);
            }
        }
#pragma unroll
        for (int j = 0; j < 8; j++) {
            float lo, hi; UNPK2(lo, hi, acc[j]);
            g_C[(8 * w + j) * 1536 + col0 + h0 + lane] = lo + hi;
        }
        if (w == 0) {
            float lo, hi; UNPK2(lo, hi, acc64);
            g_C[64 * 1536 + col0 + h0 + lane] = lo + hi;
        }
    }
}

// ------------------------- linear phase -------------------------------------
__device__ void phase_linear(float* sm, const float* __restrict__ W) {
    for (int it = blockIdx.x; it < 192; it += NB) {
        int cc = it >> 3, mtile = it & 7;
        gemm_item<4, 1>(sm, W, mtile * 64, cc * 64, 0, 0, &g_lp[cc][0]);
    }
}

// ------------------------- reduce + relu -> g_y ------------------------------
__device__ void phase_rr() {
    for (int j = blockIdx.x * NT + threadIdx.x; j < HSP / 4; j += NB * NT) {
        float4 v = __ldcg((const float4*)&g_lp[0][4 * j]);
#pragma unroll
        for (int c = 1; c < 24; c++) {
            float4 u = __ldcg((const float4*)&g_lp[c][4 * j]);
            v.x += u.x; v.y += u.y; v.z += u.z; v.w += u.w;
        }
        v.x = fmaxf(v.x, 0.f); v.y = fmaxf(v.y, 0.f);
        v.z = fmaxf(v.z, 0.f); v.w = fmaxf(v.w, 0.f);
        *(float4*)&g_y[4 * j] = v;
    }
}

// ------------------------- final chain --------------------------------------
__device__ void phase_fc1(float* sm, const float* __restrict__ W3) {   // [1536][1024]
    float* Crs = sm;
    float* Rs  = sm + 192;
    const int tid = threadIdx.x;
    for (int it = blockIdx.x; it < 64; it += NB) {
        int jt = it & 7, cc = it >> 3;
        int c0 = cc * 192, j0 = jt * 128;
        __syncthreads();
        for (int i = tid; i < 192; i += NT)
            Crs[i] = __ldcg(&g_C[64 * 1536 + c0 + i]);
        __syncthreads();
        int j = j0 + (tid & 127);
        int q = tid >> 7;
        float acc = 0.f;
#pragma unroll 4
        for (int c = q * 96; c < q * 96 + 96; c++)
            acc = fmaf(Crs[c], W3[(c0 + c) * 1024 + j], acc);
        Rs[tid] = acc;
        __syncthreads();
        if (tid < 128) g_zp[cc][j0 + tid] = Rs[tid] + Rs[tid + 128];
    }
}

__device__ void phase_ft(float* sm, const float* __restrict__ W4) {   // [1024][512]
    float* zs = sm;
    float* Rs = sm + 1024;
    const int tid = threadIdx.x, lane = tid & 31, w = tid >> 5;
    for (int it = blockIdx.x; it < 4; it += NB) {
        int h0 = it * 128;
        __syncthreads();
        for (int i = tid; i < 1024; i += NT) {
            float v = 0.f;
#pragma unroll
            for (int c = 0; c < 8; c++) v += __ldcg(&g_zp[c][i]);
            zs[i] = fmaxf(v, 0.f);
        }
        __syncthreads();
        int hh = h0 + lane * 4;
        float4 a = make_float4(0.f, 0.f, 0.f, 0.f);
#pragma unroll 4
        for (int k = w * 128; k < w * 128 + 128; k++) {
            float zv = zs[k];
            float4 wr = *(const float4*)(&W4[k * 512 + hh]);
            a.x = fmaf(zv, wr.x, a.x); a.y = fmaf(zv, wr.y, a.y);
            a.z = fmaf(zv, wr.z, a.z); a.w = fmaf(zv, wr.w, a.w);
        }
        Rs[w * 128 + lane * 4 + 0] = a.x;
        Rs[w * 128 + lane * 4 + 1] = a.y;
        Rs[w * 128 + lane * 4 + 2] = a.z;
        Rs[w * 128 + lane * 4 + 3] = a.w;
        __syncthreads();
        if (tid < 128) {
            float s = 0.f;
#pragma unroll
            for (int ww = 0; ww < 8; ww++) s += Rs[ww * 128 + tid];
            g_t[h0 + tid] = tanhf(s);
        }
    }
}

__device__ void phase_fout(float* sm, const float* __restrict__ W5,
                           float* __restrict__ out) {   // [512][64]
    float* ts = sm;
    float* Rs = sm + 512;
    const int tid = threadIdx.x, lane = tid & 31, w = tid >> 5;
    for (int i = tid; i < 512; i += NT) ts[i] = __ldcg(&g_t[i]);
    __syncthreads();
    float acc0 = 0.f, acc1 = 0.f;
    for (int k = w * 64; k < w * 64 + 64; k++) {
        float tv = ts[k];
        acc0 = fmaf(tv, W5[k * 64 + lane], acc0);
        acc1 = fmaf(tv, W5[k * 64 + 32 + lane], acc1);
    }
    Rs[w * 64 + lane] = acc0;
    Rs[w * 64 + 32 + lane] = acc1;
    __syncthreads();
    if (tid < 64) {
        float s = 0.f;
#pragma unroll
        for (int ww = 0; ww < 8; ww++) s += Rs[ww * 64 + tid];
        out[tid] = s;
    }
}

// =============================================================================
__global__ __launch_bounds__(NT, 2)
void persist_kernel(const float* __restrict__ inp, const float* __restrict__ emb,
                    const float* __restrict__ wk, const float* __restrict__ wq,
                    const float* __restrict__ wv,
                    const float* __restrict__ l1, const float* __restrict__ l2,
                    const float* __restrict__ l3, const float* __restrict__ l4,
                    const float* __restrict__ l5, float* __restrict__ out) {
    __shared__ __align__(16) float sm[SMEM_F];
    const int HH = 512 * 512 * 3;

    pf_range(wk, 786432); pf_range(wk + 1310720, 262144); pf_range(wk + 2097152, 262144);
    pf_range(wq, 786432); pf_range(wq + 1310720, 262144); pf_range(wq + 2097152, 262144);
    pf_range(wv, 786432); pf_range(wv + 1310720, 262144); pf_range(wv + 2097152, 262144);
    pf_range(l1, 786432); pf_range(l2, 786432);
    pf_range(l3, 1572864); pf_range(l4, 524288); pf_range(l5, 32768);
    pf_range(emb, 33280);

    // ---- layer 1 ----
    phase_kqv<1>(sm, wk, wq, wv, emb, inp);          gbar(0);
    phase_reduce<1>();                               gbar(1);
    phase_logits<1>(sm);                             gbar(2);
    phase_lred<1>();                                 gbar(3);
    phase_att<1>(sm);                                gbar(4);
    phase_linear(sm, l1);                            gbar(5);
    phase_rr();                                      gbar(6);
    // ---- layer 2 ----
    phase_kqv<2>(sm, wk + HH, wq + HH, wv + HH, emb, inp);  gbar(7);
    phase_reduce<2>();                               gbar(8);
    phase_logits<2>(sm);                             gbar(9);
    phase_lred<2>();                                 gbar(10);
    phase_att<2>(sm);                                gbar(11);
    phase_linear(sm, l2);                            gbar(12);
    phase_rr();                                      gbar(13);
    // ---- layer 3 ----
    phase_kqv<3>(sm, wk + 2 * HH, wq + 2 * HH, wv + 2 * HH, emb, inp);  gbar(14);
    phase_reduce<3>();                               gbar(15);
    phase_logits<3>(sm);                             gbar(16);
    phase_lred<3>();                                 gbar(17);
    phase_att<3>(sm);                                gbar(18);
    // ---- final chain ----
    phase_fc1(sm, l3);                               gbar(19);
    phase_ft(sm, l4);                                gbar(20);
    if (blockIdx.x == 0) phase_fout(sm, l5, out);
}

// ------------------------- launcher ----------------------------------------
extern "C" void kernel_launch(void* const* d_in, const int* in_sizes, int n_in,
                              void* d_out, int out_size) {
    const float *inp = 0, *emb = 0, *l3 = 0, *l4 = 0, *l5 = 0;
    const float *tri[3] = {0, 0, 0};  int ntri = 0;
    const float *pr[2]  = {0, 0};     int npr  = 0;
    for (int i = 0; i < n_in; i++) {
        const float* p = (const float*)d_in[i];
        switch (in_sizes[i]) {
            case 64:      inp = p; break;
            case 33280:   emb = p; break;
            case 2359296: if (ntri < 3) tri[ntri++] = p; break;
            case 786432:  if (npr  < 2) pr[npr++]   = p; break;
            case 1572864: l3 = p; break;
            case 524288:  l4 = p; break;
            case 32768:   l5 = p; break;
            default: break;
        }
    }
    const float *wq, *wk, *wv;
    if (n_in > 0 && in_sizes[0] == 33280) { wk = tri[0]; wq = tri[1]; wv = tri[2]; }
    else                                  { wq = tri[0]; wk = tri[1]; wv = tri[2]; }
    const float *l1 = pr[0], *l2 = pr[1];
    float* out = (float*)d_out;

    persist_kernel<<<NB, NT>>>(inp, emb, wk, wq, wv, l1, l2, l3, l4, l5, out);
}

// round 10
// speedup vs baseline: 1.2607x; 1.0199x over previous
#include <cuda_runtime.h>
#include <stdint.h>
#include <math.h>

#define NB   296
#define NT   256
#define RP   68                 // global padded row stride
#define HSP  (512*RP)
#define LSZ  (65*RP)
#define ULL  unsigned long long

// ------------------------- scratch (device globals) -------------------------
__device__ float g_y[HSP];             // current y [512][68]
__device__ float g_P[8][9][HSP];       // kqv partials [kz][mat]
__device__ float g_Lp[8][3][LSZ];      // logits partials [hcc][slot]
__device__ float g_C[65*1536];         // concat buffer
__device__ float g_lp[24][HSP];        // linear partials [cc]
__device__ float g_zp[8][1024];
__device__ float g_t[512];
__device__ ULL   g_bar[24];

// ------------------------- helpers ------------------------------------------
#define FMA2(acc, a, b) asm("fma.rn.f32x2 %0, %1, %2, %0;" : "+l"(acc) : "l"(a), "l"(b))
#define PACK2(d, x)     asm("mov.b64 %0, {%1, %1};" : "=l"(d) : "f"(x))
#define UNPK2(lo, hi, v) asm("mov.b64 {%0, %1}, %2;" : "=f"(lo), "=f"(hi) : "l"(v))

#define MMA_TF32(d, a0, a1, a2, a3, b0, b1) \
    asm("mma.sync.aligned.m16n8k8.row.col.f32.tf32.tf32.f32 " \
        "{%0,%1,%2,%3}, {%4,%5,%6,%7}, {%8,%9}, {%0,%1,%2,%3};" \
        : "+f"(d[0]), "+f"(d[1]), "+f"(d[2]), "+f"(d[3]) \
        : "r"(a0), "r"(a1), "r"(a2), "r"(a3), "r"(b0), "r"(b1))

__device__ __forceinline__ float tf32r(float f) {
    uint32_t u;
    asm("cvt.rna.tf32.f32 %0, %1;" : "=r"(u) : "f"(f));
    return __uint_as_float(u);
}

__device__ __forceinline__ void gbar(int k) {
    __threadfence();
    __syncthreads();
    if (threadIdx.x == 0) {
        ULL* p = &g_bar[k];
        ULL old, cur;
        asm volatile("atom.release.gpu.add.u64 %0, [%1], 1;"
                     : "=l"(old) : "l"(p) : "memory");
        ULL target = old - (old % (ULL)NB) + (ULL)NB;
        do {
            asm volatile("ld.acquire.gpu.u64 %0, [%1];"
                         : "=l"(cur) : "l"(p) : "memory");
        } while (cur < target);
    }
    __syncthreads();
}

__device__ __forceinline__ void pf_range(const float* p, int nfloat) {
    int lines = nfloat >> 5;
    for (int i = blockIdx.x * NT + threadIdx.x; i < lines; i += NB * NT)
        asm volatile("prefetch.global.L2 [%0];" :: "l"(p + (i << 5)));
}

// shared pool (floats):
// GEMM: A0[1152] A1[1152] B0[1152] B1[1152] Tr[4352] = 8960
// LOGITS Ks[4352] Qs[4352] Sm[4420] = 13124 ; ATT Ls[4420] Vs[2176] = 6596
#define SMEM_F 13124

// =============================================================================
// GEMM item via tf32 mma.sync m16n8k8 (see R9 header comment)
// =============================================================================
template<int MODE>
__device__ __forceinline__ void gemm_prefetch(const float* __restrict__ A,
        int mbase, int kb, const float* __restrict__ emb,
        const float* __restrict__ inp, float a4[4], float b5[5]) {
    const int tid = threadIdx.x;
    if (MODE == 1) {
        int k = tid >> 6, m = tid & 63;
#pragma unroll
        for (int r = 0; r < 4; r++)
            a4[r] = A[(kb + k + 4 * r) * 512 + mbase + m];
        int s = tid >> 4, c = tid & 15;
#pragma unroll
        for (int r = 0; r < 4; r++)
            b5[r] = __ldcg(&g_C[(s + 16 * r) * 1536 + kb + c]);
        b5[4] = (tid < 16) ? __ldcg(&g_C[64 * 1536 + kb + tid]) : 0.f;
    } else {
        int m = tid >> 4, k = tid & 15;
#pragma unroll
        for (int r = 0; r < 4; r++)
            a4[r] = A[(mbase + m + 16 * r) * 512 + kb + k];
        if (MODE == 0) {
#pragma unroll
            for (int r = 0; r < 4; r++) {
                int j = tid + 256 * r;
                b5[r] = __ldcg(&g_y[(kb + j / 65) * RP + j % 65]);
            }
            b5[4] = (tid < 16) ? __ldcg(&g_y[(kb + 15) * RP + 49 + tid]) : 0.f;
        } else {
#pragma unroll
            for (int r = 0; r < 4; r++) {
                int j = tid + 256 * r;
                int s = j % 65;
                float x = (s < 64) ? __ldg(&inp[s]) : 1.0f;
                b5[r] = emb[(kb + j / 65) * 65 + s] * x;
            }
            if (tid < 16) {
                int s = 49 + tid;
                float x = (s < 64) ? __ldg(&inp[s]) : 1.0f;
                b5[4] = emb[(kb + 15) * 65 + s] * x;
            } else b5[4] = 0.f;
        }
    }
}

template<int MODE>
__device__ __forceinline__ void gemm_store(float* At, float* Bs,
        const float a4[4], const float b5[5]) {
    const int tid = threadIdx.x;
    if (MODE == 1) {
        int k = tid >> 6, m = tid & 63;
#pragma unroll
        for (int r = 0; r < 4; r++) At[(k + 4 * r) * 72 + m] = tf32r(a4[r]);
        int s = tid >> 4, c = tid & 15;
#pragma unroll
        for (int r = 0; r < 4; r++) Bs[c * 72 + s + 16 * r] = tf32r(b5[r]);
        if (tid < 16) Bs[tid * 72 + 64] = tf32r(b5[4]);
    } else {
        int m = tid >> 4, k = tid & 15;
#pragma unroll
        for (int r = 0; r < 4; r++) At[k * 72 + m + 16 * r] = tf32r(a4[r]);
#pragma unroll
        for (int r = 0; r < 4; r++) {
            int j = tid + 256 * r;
            Bs[(j / 65) * 72 + j % 65] = tf32r(b5[r]);
        }
        if (tid < 16) Bs[15 * 72 + 49 + tid] = tf32r(b5[4]);
    }
    // zero pad columns 65..71 (16 rows x 7 cols)
    if (tid < 112) Bs[(tid / 7) * 72 + 65 + tid % 7] = 0.f;
}

template<int NCH, int MODE>
__device__ __forceinline__ void gemm_item(float* sm, const float* __restrict__ A,
        int mbase, int kb0, const float* __restrict__ emb,
        const float* __restrict__ inp, float* __restrict__ outp) {
    const int tid = threadIdx.x, lane = tid & 31, w = tid >> 5;
    const int gid = lane >> 2, tig = lane & 3;
    float* Ab0 = sm;          float* Ab1 = sm + 1152;
    float* Bb0 = sm + 2304;   float* Bb1 = sm + 3456;
    float* Tr  = sm + 4608;   // [64][68]

    float a4[4], b5[5];
    gemm_prefetch<MODE>(A, mbase, kb0, emb, inp, a4, b5);
    __syncthreads();                    // guard smem vs previous item
    gemm_store<MODE>(Ab0, Bb0, a4, b5);
    __syncthreads();

    float d[4][4];
#pragma unroll
    for (int i = 0; i < 4; i++)
#pragma unroll
        for (int j = 0; j < 4; j++) d[i][j] = 0.f;
    float d8[4] = {0.f, 0.f, 0.f, 0.f};
    const int mfw = w & 3, kfw = w >> 2;   // slice-8 assignment

#pragma unroll
    for (int c = 0; c < NCH; c++) {
        if (c + 1 < NCH)
            gemm_prefetch<MODE>(A, mbase, kb0 + (c + 1) * 16, emb, inp, a4, b5);
        const float* At = (c & 1) ? Ab1 : Ab0;
        const float* Bs = (c & 1) ? Bb1 : Bb0;
#pragma unroll
        for (int kf = 0; kf < 2; kf++) {
            int kr = kf * 8;
            uint32_t b0 = __float_as_uint(Bs[(kr + tig) * 72 + 8 * w + gid]);
            uint32_t b1 = __float_as_uint(Bs[(kr + tig + 4) * 72 + 8 * w + gid]);
#pragma unroll
            for (int mf = 0; mf < 4; mf++) {
                int mc = mf * 16 + gid;
                uint32_t a0 = __float_as_uint(At[(kr + tig) * 72 + mc]);
                uint32_t a1 = __float_as_uint(At[(kr + tig) * 72 + mc + 8]);
                uint32_t a2 = __float_as_uint(At[(kr + tig + 4) * 72 + mc]);
                uint32_t a3 = __float_as_uint(At[(kr + tig + 4) * 72 + mc + 8]);
                MMA_TF32(d[mf], a0, a1, a2, a3, b0, b1);
            }
        }
        {   // slice 8 (cols 64-71): this warp's (mfw, kfw) fragment
            int kr = kfw * 8;
            uint32_t b0 = __float_as_uint(Bs[(kr + tig) * 72 + 64 + gid]);
            uint32_t b1 = __float_as_uint(Bs[(kr + tig + 4) * 72 + 64 + gid]);
            int mc = mfw * 16 + gid;
            uint32_t a0 = __float_as_uint(At[(kr + tig) * 72 + mc]);
            uint32_t a1 = __float_as_uint(At[(kr + tig) * 72 + mc + 8]);
            uint32_t a2 = __float_as_uint(At[(kr + tig + 4) * 72 + mc]);
            uint32_t a3 = __float_as_uint(At[(kr + tig + 4) * 72 + mc + 8]);
            MMA_TF32(d8, a0, a1, a2, a3, b0, b1);
        }
        if (c + 1 < NCH) {
            gemm_store<MODE>((c & 1) ? Ab0 : Ab1, (c & 1) ? Bb0 : Bb1, a4, b5);
            __syncthreads();
        }
    }
    // main-slice D -> Tr (cols 0-63)
#pragma unroll
    for (int mf = 0; mf < 4; mf++) {
        int cc = 8 * w + tig * 2;
        *(float2*)&Tr[(mf * 16 + gid) * RP + cc]     = make_float2(d[mf][0], d[mf][1]);
        *(float2*)&Tr[(mf * 16 + gid + 8) * RP + cc] = make_float2(d[mf][2], d[mf][3]);
    }
    // slice-8: kfrag 0 stores, kfrag 1 adds (cols 64-67; cols >=68 are zero)
    if (kfw == 0 && tig < 2) {
        *(float2*)&Tr[(mfw * 16 + gid) * RP + 64 + tig * 2]     = make_float2(d8[0], d8[1]);
        *(float2*)&Tr[(mfw * 16 + gid + 8) * RP + 64 + tig * 2] = make_float2(d8[2], d8[3]);
    }
    __syncthreads();
    if (kfw == 1 && tig < 2) {
        float2* p0 = (float2*)&Tr[(mfw * 16 + gid) * RP + 64 + tig * 2];
        float2 v0 = *p0; v0.x += d8[0]; v0.y += d8[1]; *p0 = v0;
        float2* p1 = (float2*)&Tr[(mfw * 16 + gid + 8) * RP + 64 + tig * 2];
        float2 v1 = *p1; v1.x += d8[2]; v1.y += d8[3]; *p1 = v1;
    }
    __syncthreads();
    for (int i = tid; i < 64 * RP; i += NT)
        outp[mbase * RP + i] = Tr[i];
}

// ------------------------- kqv phase ----------------------------------------
template<int LAYER>
__device__ void phase_kqv(float* sm, const float* __restrict__ wK,
                          const float* __restrict__ wQ, const float* __restrict__ wV,
                          const float* __restrict__ emb, const float* __restrict__ inp) {
    constexpr int nmats = (LAYER == 1) ? 9 : 3;
    constexpr int nkz   = (LAYER == 1) ? 4 : 8;
    constexpr int kspan = 512 / nkz;
    constexpr int per   = nmats * 8;
    constexpr int items = per * nkz;
    for (int it = blockIdx.x; it < items; it += NB) {
        int kz = it / per, rem = it - kz * per;
        int mat = rem >> 3, mtile = rem & 7;
        int type = (LAYER == 1) ? (mat % 3) : mat;
        int head = (LAYER == 1) ? (mat / 3) : 2;
        const float* A = ((type == 0) ? wK : (type == 1) ? wQ : wV) + head * 262144;
        gemm_item<kspan / 16, (LAYER == 1) ? 2 : 0>(sm, A, mtile * 64, kz * kspan,
                                                    emb, inp, &g_P[kz][mat][0]);
    }
}

// ------------ logits phase (h-chunk 64; folds kz partials at load) ----------
template<int LAYER>
__device__ void phase_logits(float* sm) {
    float* Ks = sm;            // [64][68]
    float* Qs = sm + 4352;
    float* Sm = sm + 8704;     // [65][68]
    const int tid = threadIdx.x, lane = tid & 31, w = tid >> 5;
    constexpr int slots = (LAYER == 1) ? 3 : 1;
    constexpr int nz    = (LAYER == 1) ? 4 : 8;
    constexpr int items = slots * 8;
    for (int it = blockIdx.x; it < items; it += NB) {
        int slot = it >> 3, hcc = it & 7, h0 = hcc * 64;
        int matK = (LAYER == 1) ? slot * 3 : 0;
        int matQ = matK + 1;
        __syncthreads();
        for (int i = tid; i < 1088; i += NT) {
            float4 k4 = __ldcg((const float4*)&g_P[0][matK][h0 * RP + 4 * i]);
            float4 q4 = __ldcg((const float4*)&g_P[0][matQ][h0 * RP + 4 * i]);
#pragma unroll
            for (int z = 1; z < nz; z++) {
                float4 u = __ldcg((const float4*)&g_P[z][matK][h0 * RP + 4 * i]);
                k4.x += u.x; k4.y += u.y; k4.z += u.z; k4.w += u.w;
                float4 v = __ldcg((const float4*)&g_P[z][matQ][h0 * RP + 4 * i]);
                q4.x += v.x; q4.y += v.y; q4.z += v.z; q4.w += v.w;
            }
            *(float4*)&Ks[4 * i] = k4;
            *(float4*)&Qs[4 * i] = q4;
        }
        if (tid < 65) { Sm[tid * RP + 65] = 0.f; Sm[tid * RP + 66] = 0.f; Sm[tid * RP + 67] = 0.f; }
        __syncthreads();
        ULL r0[4] = {0,0,0,0}, r1[4] = {0,0,0,0}, r2[4] = {0,0,0,0};
        float u0 = 0.f, u1 = 0.f, u2 = 0.f;
        for (int h = 0; h < 64; h++) {
            float k0 = Ks[h * RP + lane];
            float k1 = Ks[h * RP + 32 + lane];
            float k2 = Ks[h * RP + 64];
            ULL p0, p1, p2;
            PACK2(p0, k0); PACK2(p1, k1); PACK2(p2, k2);
            ulonglong2 qa = *(const ulonglong2*)(Qs + h * RP + 8 * w);
            ulonglong2 qb = *(const ulonglong2*)(Qs + h * RP + 8 * w + 4);
            FMA2(r0[0], p0, qa.x); FMA2(r0[1], p0, qa.y);
            FMA2(r0[2], p0, qb.x); FMA2(r0[3], p0, qb.y);
            FMA2(r1[0], p1, qa.x); FMA2(r1[1], p1, qa.y);
            FMA2(r1[2], p1, qb.x); FMA2(r1[3], p1, qb.y);
            FMA2(r2[0], p2, qa.x); FMA2(r2[1], p2, qa.y);
            FMA2(r2[2], p2, qb.x); FMA2(r2[3], p2, qb.y);
            if (w == 0) {
                float q64 = Qs[h * RP + 64];
                u0 = fmaf(k0, q64, u0); u1 = fmaf(k1, q64, u1); u2 = fmaf(k2, q64, u2);
            }
        }
        *(ulonglong2*)(Sm + lane * RP + 8 * w)     = make_ulonglong2(r0[0], r0[1]);
        *(ulonglong2*)(Sm + lane * RP + 8 * w + 4) = make_ulonglong2(r0[2], r0[3]);
        *(ulonglong2*)(Sm + (lane + 32) * RP + 8 * w)     = make_ulonglong2(r1[0], r1[1]);
        *(ulonglong2*)(Sm + (lane + 32) * RP + 8 * w + 4) = make_ulonglong2(r1[2], r1[3]);
        if (lane == 0) {
            *(ulonglong2*)(Sm + 64 * RP + 8 * w)     = make_ulonglong2(r2[0], r2[1]);
            *(ulonglong2*)(Sm + 64 * RP + 8 * w + 4) = make_ulonglong2(r2[2], r2[3]);
        }
        if (w == 0) {
            Sm[lane * RP + 64] = u0;
            Sm[(lane + 32) * RP + 64] = u1;
            if (lane == 0) Sm[64 * RP + 64] = u2;
        }
        __syncthreads();
        float* Lp = &g_Lp[hcc][slot][0];
        for (int i = tid; i < LSZ; i += NT) Lp[i] = Sm[i];
    }
}

// ---- att phase (softmax fused; folds hcc logits partials + kz V partials) --
template<int LAYER>
__device__ void phase_att(float* sm) {
    float* Ls = sm;            // [65][68]
    float* Vs = sm + 4420;     // [32][68]
    const int tid = threadIdx.x, lane = tid & 31, w = tid >> 5;
    constexpr int slots = (LAYER == 1) ? 3 : 1;
    constexpr int nz    = (LAYER == 1) ? 4 : 8;
    constexpr int items = slots * 16;
    for (int it = blockIdx.x; it < items; it += NB) {
        int slot = it >> 4, hc = it & 15, h0 = hc * 32;
        int matV = (LAYER == 1) ? slot * 3 + 2 : 2;
        int col0 = (LAYER == 1) ? slot * 512 : 1024;
        __syncthreads();
        for (int i = tid; i < 1105; i += NT) {
            float4 l4 = __ldcg((const float4*)&g_Lp[0][slot][0] + i);
#pragma unroll
            for (int c = 1; c < 8; c++) {
                float4 u = __ldcg((const float4*)&g_Lp[c][slot][0] + i);
                l4.x += u.x; l4.y += u.y; l4.z += u.z; l4.w += u.w;
            }
            ((float4*)Ls)[i] = l4;
        }
        for (int i = tid; i < 544; i += NT) {
            float4 v4 = __ldcg((const float4*)&g_P[0][matV][h0 * RP] + i);
#pragma unroll
            for (int z = 1; z < nz; z++) {
                float4 u = __ldcg((const float4*)&g_P[z][matV][h0 * RP] + i);
                v4.x += u.x; v4.y += u.y; v4.z += u.z; v4.w += u.w;
            }
            ((float4*)Vs)[i] = v4;
        }
        __syncthreads();
        if (tid < 32) { Vs[tid * RP + 65] = 0.f; Vs[tid * RP + 66] = 0.f; Vs[tid * RP + 67] = 0.f; }
        __syncthreads();
        for (int a = w; a < 65; a += 8) {
            float e0 = Ls[a * RP + lane];
            float e1 = Ls[a * RP + 32 + lane];
            float e2 = (lane == 0) ? Ls[a * RP + 64] : -3.0e38f;
            float mx = fmaxf(e0, fmaxf(e1, e2));
#pragma unroll
            for (int off = 16; off > 0; off >>= 1)
                mx = fmaxf(mx, __shfl_xor_sync(0xffffffffu, mx, off));
            float x0 = expf(e0 - mx);
            float x1 = expf(e1 - mx);
            float x2 = (lane == 0) ? expf(e2 - mx) : 0.f;
            float ssum = x0 + x1 + x2;
#pragma unroll
            for (int off = 16; off > 0; off >>= 1)
                ssum += __shfl_xor_sync(0xffffffffu, ssum, off);
            float inv = 1.0f / ssum;
            Ls[a * RP + lane] = x0 * inv;
            Ls[a * RP + 32 + lane] = x1 * inv;
            if (lane == 0) Ls[a * RP + 64] = x2 * inv;
        }
        __syncthreads();
        ULL acc[8] = {0,0,0,0,0,0,0,0};
        ULL acc64 = 0;
        const float* Vrow = Vs + lane * RP;
        for (int p = 0; p < 34; p++) {
            ULL vv = *(const ULL*)(Vrow + 2 * p);
#pragma unroll
            for (int j = 0; j < 8; j++) {
                ULL lp = *(const ULL*)(Ls + (8 * w + j) * RP + 2 * p);
                FMA2(acc[j], lp, vv);
            }
            if (w == 0) {
                ULL l64 = *(const ULL*)(Ls + 64 * RP + 2 * p);
                FMA2(acc64, l64, vv);
            }
        }
#pragma unroll
        for (int j = 0; j < 8; j++) {
            float lo, hi; UNPK2(lo, hi, acc[j]);
            g_C[(8 * w + j) * 1536 + col0 + h0 + lane] = lo + hi;
        }
        if (w == 0) {
            float lo, hi; UNPK2(lo, hi, acc64);
            g_C[64 * 1536 + col0 + h0 + lane] = lo + hi;
        }
    }
}

// ------------------------- linear phase -------------------------------------
__device__ void phase_linear(float* sm, const float* __restrict__ W) {
    for (int it = blockIdx.x; it < 192; it += NB) {
        int cc = it >> 3, mtile = it & 7;
        gemm_item<4, 1>(sm, W, mtile * 64, cc * 64, 0, 0, &g_lp[cc][0]);
    }
}

// ------------------------- reduce + relu -> g_y ------------------------------
__device__ void phase_rr() {
    for (int j = blockIdx.x * NT + threadIdx.x; j < HSP / 4; j += NB * NT) {
        float4 v = __ldcg((const float4*)&g_lp[0][4 * j]);
#pragma unroll
        for (int c = 1; c < 24; c++) {
            float4 u = __ldcg((const float4*)&g_lp[c][4 * j]);
            v.x += u.x; v.y += u.y; v.z += u.z; v.w += u.w;
        }
        v.x = fmaxf(v.x, 0.f); v.y = fmaxf(v.y, 0.f);
        v.z = fmaxf(v.z, 0.f); v.w = fmaxf(v.w, 0.f);
        *(float4*)&g_y[4 * j] = v;
    }
}

// ------------------------- final chain --------------------------------------
__device__ void phase_fc1(float* sm, const float* __restrict__ W3) {   // [1536][1024]
    float* Crs = sm;
    float* Rs  = sm + 192;
    const int tid = threadIdx.x;
    for (int it = blockIdx.x; it < 64; it += NB) {
        int jt = it & 7, cc = it >> 3;
        int c0 = cc * 192, j0 = jt * 128;
        __syncthreads();
        for (int i = tid; i < 192; i += NT)
            Crs[i] = __ldcg(&g_C[64 * 1536 + c0 + i]);
        __syncthreads();
        int j = j0 + (tid & 127);
        int q = tid >> 7;
        float acc = 0.f;
#pragma unroll 4
        for (int c = q * 96; c < q * 96 + 96; c++)
            acc = fmaf(Crs[c], W3[(c0 + c) * 1024 + j], acc);
        Rs[tid] = acc;
        __syncthreads();
        if (tid < 128) g_zp[cc][j0 + tid] = Rs[tid] + Rs[tid + 128];
    }
}

__device__ void phase_ft(float* sm, const float* __restrict__ W4) {   // [1024][512]
    float* zs = sm;
    float* Rs = sm + 1024;
    const int tid = threadIdx.x, lane = tid & 31, w = tid >> 5;
    for (int it = blockIdx.x; it < 4; it += NB) {
        int h0 = it * 128;
        __syncthreads();
        for (int i = tid; i < 1024; i += NT) {
            float v = 0.f;
#pragma unroll
            for (int c = 0; c < 8; c++) v += __ldcg(&g_zp[c][i]);
            zs[i] = fmaxf(v, 0.f);
        }
        __syncthreads();
        int hh = h0 + lane * 4;
        float4 a = make_float4(0.f, 0.f, 0.f, 0.f);
#pragma unroll 4
        for (int k = w * 128; k < w * 128 + 128; k++) {
            float zv = zs[k];
            float4 wr = *(const float4*)(&W4[k * 512 + hh]);
            a.x = fmaf(zv, wr.x, a.x); a.y = fmaf(zv, wr.y, a.y);
            a.z = fmaf(zv, wr.z, a.z); a.w = fmaf(zv, wr.w, a.w);
        }
        Rs[w * 128 + lane * 4 + 0] = a.x;
        Rs[w * 128 + lane * 4 + 1] = a.y;
        Rs[w * 128 + lane * 4 + 2] = a.z;
        Rs[w * 128 + lane * 4 + 3] = a.w;
        __syncthreads();
        if (tid < 128) {
            float s = 0.f;
#pragma unroll
            for (int ww = 0; ww < 8; ww++) s += Rs[ww * 128 + tid];
            g_t[h0 + tid] = tanhf(s);
        }
    }
}

__device__ void phase_fout(float* sm, const float* __restrict__ W5,
                           float* __restrict__ out) {   // [512][64]
    float* ts = sm;
    float* Rs = sm + 512;
    const int tid = threadIdx.x, lane = tid & 31, w = tid >> 5;
    for (int i = tid; i < 512; i += NT) ts[i] = __ldcg(&g_t[i]);
    __syncthreads();
    float acc0 = 0.f, acc1 = 0.f;
    for (int k = w * 64; k < w * 64 + 64; k++) {
        float tv = ts[k];
        acc0 = fmaf(tv, W5[k * 64 + lane], acc0);
        acc1 = fmaf(tv, W5[k * 64 + 32 + lane], acc1);
    }
    Rs[w * 64 + lane] = acc0;
    Rs[w * 64 + 32 + lane] = acc1;
    __syncthreads();
    if (tid < 64) {
        float s = 0.f;
#pragma unroll
        for (int ww = 0; ww < 8; ww++) s += Rs[ww * 64 + tid];
        out[tid] = s;
    }
}

// =============================================================================
__global__ __launch_bounds__(NT, 2)
void persist_kernel(const float* __restrict__ inp, const float* __restrict__ emb,
                    const float* __restrict__ wk, const float* __restrict__ wq,
                    const float* __restrict__ wv,
                    const float* __restrict__ l1, const float* __restrict__ l2,
                    const float* __restrict__ l3, const float* __restrict__ l4,
                    const float* __restrict__ l5, float* __restrict__ out) {
    __shared__ __align__(16) float sm[SMEM_F];
    const int HH = 512 * 512 * 3;

    pf_range(wk, 786432); pf_range(wk + 1310720, 262144); pf_range(wk + 2097152, 262144);
    pf_range(wq, 786432); pf_range(wq + 1310720, 262144); pf_range(wq + 2097152, 262144);
    pf_range(wv, 786432); pf_range(wv + 1310720, 262144); pf_range(wv + 2097152, 262144);
    pf_range(l1, 786432); pf_range(l2, 786432);
    pf_range(l3, 1572864); pf_range(l4, 524288); pf_range(l5, 32768);
    pf_range(emb, 33280);

    // ---- layer 1 ----
    phase_kqv<1>(sm, wk, wq, wv, emb, inp);          gbar(0);
    phase_logits<1>(sm);                             gbar(1);
    phase_att<1>(sm);                                gbar(2);
    phase_linear(sm, l1);                            gbar(3);
    phase_rr();                                      gbar(4);
    // ---- layer 2 ----
    phase_kqv<2>(sm, wk + HH, wq + HH, wv + HH, emb, inp);  gbar(5);
    phase_logits<2>(sm);                             gbar(6);
    phase_att<2>(sm);                                gbar(7);
    phase_linear(sm, l2);                            gbar(8);
    phase_rr();                                      gbar(9);
    // ---- layer 3 ----
    phase_kqv<3>(sm, wk + 2 * HH, wq + 2 * HH, wv + 2 * HH, emb, inp);  gbar(10);
    phase_logits<3>(sm);                             gbar(11);
    phase_att<3>(sm);                                gbar(12);
    // ---- final chain ----
    phase_fc1(sm, l3);                               gbar(13);
    phase_ft(sm, l4);                                gbar(14);
    if (blockIdx.x == 0) phase_fout(sm, l5, out);
}

// ------------------------- launcher ----------------------------------------
extern "C" void kernel_launch(void* const* d_in, const int* in_sizes, int n_in,
                              void* d_out, int out_size) {
    const float *inp = 0, *emb = 0, *l3 = 0, *l4 = 0, *l5 = 0;
    const float *tri[3] = {0, 0, 0};  int ntri = 0;
    const float *pr[2]  = {0, 0};     int npr  = 0;
    for (int i = 0; i < n_in; i++) {
        const float* p = (const float*)d_in[i];
        switch (in_sizes[i]) {
            case 64:      inp = p; break;
            case 33280:   emb = p; break;
            case 2359296: if (ntri < 3) tri[ntri++] = p; break;
            case 786432:  if (npr  < 2) pr[npr++]   = p; break;
            case 1572864: l3 = p; break;
            case 524288:  l4 = p; break;
            case 32768:   l5 = p; break;
            default: break;
        }
    }
    const float *wq, *wk, *wv;
    if (n_in > 0 && in_sizes[0] == 33280) { wk = tri[0]; wq = tri[1]; wv = tri[2]; }
    else                                  { wq = tri[0]; wk = tri[1]; wv = tri[2]; }
    const float *l1 = pr[0], *l2 = pr[1];
    float* out = (float*)d_out;

    persist_kernel<<<NB, NT>>>(inp, emb, wk, wq, wv, l1, l2, l3, l4, l5, out);
}